// round 2
// baseline (speedup 1.0000x reference)
#include <cuda_runtime.h>
#include <cuda_fp16.h>
#include <cstdint>

// ============================================================================
// Problem dims
// ============================================================================
static constexpr int NTOK = 8192;   // tokens (M)
static constexpr int KDIM = 4096;   // input dim  (a1*b1)
static constexpr int NDIM = 4096;   // output dim (a2*b2)

// Scratch (allocation-free rule: __device__ globals)
__device__ __half g_wt[(size_t)NDIM * KDIM];  // W^T: [n][k] fp16
__device__ __half g_xh[(size_t)NTOK * KDIM];  // x:   [m][k] fp16

// ============================================================================
// PTX helpers (sm_103 baseline only — NO tcgen05 / 'a' features)
// ============================================================================
__device__ __forceinline__ uint32_t smem_to_u32(const void* smem_ptr) {
    uint32_t addr;
    asm("{ .reg .u64 tmp; cvta.to.shared.u64 tmp, %1; cvt.u32.u64 %0, tmp; }"
        : "=r"(addr) : "l"(smem_ptr));
    return addr;
}

#define CP_ASYNC16(smem_u32, gptr) \
    asm volatile("cp.async.cg.shared.global [%0], [%1], 16;\n" \
                 :: "r"(smem_u32), "l"(gptr))
#define CP_COMMIT() asm volatile("cp.async.commit_group;\n" ::: "memory")
#define CP_WAIT(n)  asm volatile("cp.async.wait_group %0;\n" :: "n"(n) : "memory")

__device__ __forceinline__ void ldmx4(uint32_t* r, uint32_t addr) {
    asm volatile("ldmatrix.sync.aligned.m8n8.x4.shared.b16 {%0,%1,%2,%3}, [%4];"
                 : "=r"(r[0]), "=r"(r[1]), "=r"(r[2]), "=r"(r[3])
                 : "r"(addr));
}

__device__ __forceinline__ void mma16816(float* d, const uint32_t* a,
                                         uint32_t b0, uint32_t b1) {
    asm volatile(
        "mma.sync.aligned.m16n8k16.row.col.f32.f16.f16.f32 "
        "{%0,%1,%2,%3}, {%4,%5,%6,%7}, {%8,%9}, {%0,%1,%2,%3};"
        : "+f"(d[0]), "+f"(d[1]), "+f"(d[2]), "+f"(d[3])
        : "r"(a[0]), "r"(a[1]), "r"(a[2]), "r"(a[3]), "r"(b0), "r"(b1));
}

// 64B rows (32 halves), 4 x 16B chunks, swizzle chunk ^= (row>>1)&3
// -> conflict-free for both cp.async 16B stores and ldmatrix reads.
__device__ __forceinline__ uint32_t swz(uint32_t row, uint32_t c) {
    return row * 64u + ((c ^ ((row >> 1) & 3u)) * 16u);
}

// ============================================================================
// Kernel 1: build W^T[n][k] in fp16.
//   n = j*64 + l, k = i*64 + k2;  Wt[n][k] = sum_r a[r,i,j] * b[r,k2,l]
// ============================================================================
__global__ void __launch_bounds__(256) build_wt_kernel(
    const float* __restrict__ a, const float* __restrict__ b)
{
    __shared__ float a_s[64 * 64];  // [r][i]
    __shared__ float b_s[64 * 64];  // [r][k2]
    const int n = blockIdx.x;
    const int j = n >> 6, l = n & 63;
    const int tid = threadIdx.x;

    #pragma unroll
    for (int idx = tid; idx < 4096; idx += 256) {
        int r = idx >> 6, c = idx & 63;
        a_s[idx] = a[r * 4096 + c * 64 + j];
        b_s[idx] = b[r * 4096 + c * 64 + l];
    }
    __syncthreads();

    const int base = tid * 16;
    const int i  = base >> 6;
    const int k0 = base & 63;

    float acc[16];
    #pragma unroll
    for (int q = 0; q < 16; q++) acc[q] = 0.0f;

    #pragma unroll 8
    for (int r = 0; r < 64; r++) {
        float av = a_s[r * 64 + i];
        const float* bp = &b_s[r * 64 + k0];
        #pragma unroll
        for (int q = 0; q < 16; q++) acc[q] = fmaf(av, bp[q], acc[q]);
    }

    __half2* dst = reinterpret_cast<__half2*>(&g_wt[(size_t)n * KDIM + base]);
    #pragma unroll
    for (int q = 0; q < 8; q++)
        dst[q] = __floats2half2_rn(acc[2 * q], acc[2 * q + 1]);
}

// ============================================================================
// Kernel 2: x fp32 -> fp16
// ============================================================================
__global__ void __launch_bounds__(256) convert_x_kernel(const float* __restrict__ x)
{
    const size_t total4 = (size_t)NTOK * KDIM / 4;
    size_t i = (size_t)blockIdx.x * blockDim.x + threadIdx.x;
    const size_t stride = (size_t)gridDim.x * blockDim.x;
    __half2* dst = reinterpret_cast<__half2*>(g_xh);
    for (; i < total4; i += stride) {
        float4 v = reinterpret_cast<const float4*>(x)[i];
        dst[2 * i + 0] = __floats2half2_rn(v.x, v.y);
        dst[2 * i + 1] = __floats2half2_rn(v.z, v.w);
    }
}

// ============================================================================
// Kernel 3: mma.sync fp16 GEMM
//   out[m][n] = sum_k Xh[m][k] * Wt[n][k] + bias[n]
// Tile 256x128x32, 4 cp.async stages, 8 warps (4x2), warp tile 64x64.
// ============================================================================
static constexpr int BM = 256, BN = 128, BK = 32;
static constexpr int STAGES = 4;
static constexpr int A_STAGE = BM * BK * 2;   // 16384 B
static constexpr int B_STAGE = BN * BK * 2;   //  8192 B
static constexpr int GEMM_SMEM = STAGES * (A_STAGE + B_STAGE);  // 98304 B

__global__ void __launch_bounds__(256, 1) kron_gemm_kernel(
    float* __restrict__ out, const float* __restrict__ bias)
{
    extern __shared__ char smem[];
    const uint32_t smA = smem_to_u32(smem);
    const uint32_t smB = smA + STAGES * A_STAGE;

    const int tid  = threadIdx.x;
    const int wid  = tid >> 5;
    const int lane = tid & 31;
    const int wm   = wid & 3;   // 0..3 -> M
    const int wn   = wid >> 2;  // 0..1 -> N
    const int mBase = blockIdx.y * BM;
    const int nBase = blockIdx.x * BN;

    const __half* Ag = g_xh + (size_t)mBase * KDIM;
    const __half* Bg = g_wt + (size_t)nBase * KDIM;

    // Per-thread cp.async coordinates (fixed across stages)
    const int a_row0 = tid >> 2;       // + it*64
    const int a_c    = tid & 3;

    auto load_stage = [&](int kb, int slot) {
        const __half* Ak = Ag + kb * BK;
        const __half* Bk = Bg + kb * BK;
        uint32_t sA = smA + slot * A_STAGE;
        uint32_t sB = smB + slot * B_STAGE;
        #pragma unroll
        for (int it = 0; it < 4; it++) {
            int row = a_row0 + it * 64;
            CP_ASYNC16(sA + swz(row, a_c), Ak + (size_t)row * KDIM + a_c * 8);
        }
        #pragma unroll
        for (int it = 0; it < 2; it++) {
            int row = a_row0 + it * 64;
            CP_ASYNC16(sB + swz(row, a_c), Bk + (size_t)row * KDIM + a_c * 8);
        }
        CP_COMMIT();
    };

    #pragma unroll
    for (int s = 0; s < STAGES - 1; s++) load_stage(s, s);

    float acc[4][8][4] = {};

    // ldmatrix lane coordinates (fixed): row within tile + k-chunk half
    const int lm_row = lane & 15;     // row offset within 16-row tile
    const int lm_hi  = lane >> 4;     // 0/1 -> k chunk within k16

    const int KITERS = KDIM / BK;     // 128
    #pragma unroll 1
    for (int kb = 0; kb < KITERS; kb++) {
        CP_WAIT(STAGES - 2);
        __syncthreads();

        const int slot = kb & (STAGES - 1);
        if (kb + STAGES - 1 < KITERS)
            load_stage(kb + STAGES - 1, (kb + STAGES - 1) & (STAGES - 1));
        else
            CP_COMMIT();   // keep group counting consistent

        const uint32_t sA = smA + slot * A_STAGE;
        const uint32_t sB = smB + slot * B_STAGE;

        #pragma unroll
        for (int s = 0; s < 2; s++) {          // two k16 steps per BK=32
            const int c = s * 2 + lm_hi;
            uint32_t afrag[4][4];
            uint32_t bfrag[4][4];
            #pragma unroll
            for (int mi = 0; mi < 4; mi++) {
                int row = wm * 64 + mi * 16 + lm_row;
                ldmx4(afrag[mi], sA + swz(row, c));
            }
            #pragma unroll
            for (int ni = 0; ni < 4; ni++) {
                int row = wn * 64 + ni * 16 + lm_row;
                ldmx4(bfrag[ni], sB + swz(row, c));
            }
            #pragma unroll
            for (int mi = 0; mi < 4; mi++) {
                #pragma unroll
                for (int nj = 0; nj < 8; nj++) {
                    const uint32_t* bg = bfrag[nj >> 1];
                    uint32_t b0 = (nj & 1) ? bg[1] : bg[0];
                    uint32_t b1 = (nj & 1) ? bg[3] : bg[2];
                    mma16816(acc[mi][nj], afrag[mi], b0, b1);
                }
            }
        }
    }

    // Epilogue: D frag mapping — thread t: rows (t/4, t/4+8), cols 2*(t%4)+{0,1}
    const int gr = lane >> 2;
    const int gc = (lane & 3) * 2;
    #pragma unroll
    for (int mi = 0; mi < 4; mi++) {
        const int m0 = mBase + wm * 64 + mi * 16 + gr;
        float* r0p = out + (size_t)m0 * NDIM;
        float* r1p = out + (size_t)(m0 + 8) * NDIM;
        #pragma unroll
        for (int nj = 0; nj < 8; nj++) {
            const int n0 = nBase + wn * 64 + nj * 8 + gc;
            const float b0 = __ldg(&bias[n0]);
            const float b1 = __ldg(&bias[n0 + 1]);
            float2 v0 = make_float2(acc[mi][nj][0] + b0, acc[mi][nj][1] + b1);
            float2 v1 = make_float2(acc[mi][nj][2] + b0, acc[mi][nj][3] + b1);
            *reinterpret_cast<float2*>(r0p + n0) = v0;
            *reinterpret_cast<float2*>(r1p + n0) = v1;
        }
    }
}

// ============================================================================
// kernel_launch
// Inputs (metadata order): x (8192*4096 f32), a (64*64*64 f32),
//                          b (64*64*64 f32), bias (4096 f32)
// Output: 8192*4096 f32
// ============================================================================
extern "C" void kernel_launch(void* const* d_in, const int* in_sizes, int n_in,
                              void* d_out, int out_size)
{
    const float* x    = (const float*)d_in[0];
    const float* a    = (const float*)d_in[1];
    const float* b    = (const float*)d_in[2];
    const float* bias = (const float*)d_in[3];
    float* out = (float*)d_out;

    static bool attr_set = false;
    if (!attr_set) {
        cudaFuncSetAttribute(kron_gemm_kernel,
                             cudaFuncAttributeMaxDynamicSharedMemorySize,
                             GEMM_SMEM);
        attr_set = true;
    }

    // 1. Materialize W^T in fp16
    build_wt_kernel<<<NDIM, 256>>>(a, b);

    // 2. Convert x to fp16
    convert_x_kernel<<<2048, 256>>>(x);

    // 3. Pipelined mma.sync fp16 GEMM with fused bias epilogue
    dim3 grid(NDIM / BN, NTOK / BM);   // (32, 32)
    kron_gemm_kernel<<<grid, 256, GEMM_SMEM>>>(out, bias);
}

// round 3
// speedup vs baseline: 1.5408x; 1.5408x over previous
#include <cuda_runtime.h>
#include <cuda_fp16.h>
#include <cstdint>

// ============================================================================
// Problem dims
// ============================================================================
static constexpr int NTOK = 8192;   // tokens (M)
static constexpr int KDIM = 4096;   // input dim  (a1*b1)
static constexpr int NDIM = 4096;   // output dim (a2*b2)

// Scratch (allocation-free rule: __device__ globals)
__device__ __half g_wt[(size_t)NDIM * KDIM];  // W^T: [n][k] fp16
__device__ __half g_xh[(size_t)NTOK * KDIM];  // x:   [m][k] fp16
__device__ float  g_at[64 * 64 * 64];         // at[j][r][i] = a[r,i,j]
__device__ float  g_bt[64 * 64 * 64];         // bt[l][r][k2] = b[r,k2,l]

// ============================================================================
// PTX helpers (sm_103 baseline only — NO tcgen05 / 'a' features)
// ============================================================================
__device__ __forceinline__ uint32_t smem_to_u32(const void* smem_ptr) {
    uint32_t addr;
    asm("{ .reg .u64 tmp; cvta.to.shared.u64 tmp, %1; cvt.u32.u64 %0, tmp; }"
        : "=r"(addr) : "l"(smem_ptr));
    return addr;
}

#define CP_ASYNC16(smem_u32, gptr) \
    asm volatile("cp.async.cg.shared.global [%0], [%1], 16;\n" \
                 :: "r"(smem_u32), "l"(gptr))
#define CP_COMMIT() asm volatile("cp.async.commit_group;\n" ::: "memory")
#define CP_WAIT(n)  asm volatile("cp.async.wait_group %0;\n" :: "n"(n) : "memory")

__device__ __forceinline__ void ldmx4(uint32_t* r, uint32_t addr) {
    asm volatile("ldmatrix.sync.aligned.m8n8.x4.shared.b16 {%0,%1,%2,%3}, [%4];"
                 : "=r"(r[0]), "=r"(r[1]), "=r"(r[2]), "=r"(r[3])
                 : "r"(addr));
}

__device__ __forceinline__ void mma16816(float* d, const uint32_t* a,
                                         uint32_t b0, uint32_t b1) {
    asm volatile(
        "mma.sync.aligned.m16n8k16.row.col.f32.f16.f16.f32 "
        "{%0,%1,%2,%3}, {%4,%5,%6,%7}, {%8,%9}, {%0,%1,%2,%3};"
        : "+f"(d[0]), "+f"(d[1]), "+f"(d[2]), "+f"(d[3])
        : "r"(a[0]), "r"(a[1]), "r"(a[2]), "r"(a[3]), "r"(b0), "r"(b1));
}

// 64B rows (32 halves), 4 x 16B chunks, swizzle chunk ^= (row>>1)&3
// -> conflict-free for both cp.async 16B stores and ldmatrix reads.
__device__ __forceinline__ uint32_t swz(uint32_t row, uint32_t c) {
    return row * 64u + ((c ^ ((row >> 1) & 3u)) * 16u);
}

// ============================================================================
// Kernel 0: transpose a -> at[j][r][i], b -> bt[l][r][k2]
// Blocks 0..63: r-slice of a.  Blocks 64..127: r-slice of b.
// Coalesced global reads AND writes (smem-tiled transpose, padded rows).
// ============================================================================
__global__ void __launch_bounds__(256) transpose_ab_kernel(
    const float* __restrict__ a, const float* __restrict__ b)
{
    __shared__ float s[64 * 65];
    const int r = blockIdx.x & 63;
    const bool isA = blockIdx.x < 64;
    const float* src = (isA ? a : b) + (size_t)r * 4096;
    float* dst = isA ? g_at : g_bt;
    const int tid = threadIdx.x;

    #pragma unroll
    for (int idx = tid; idx < 4096; idx += 256)
        s[(idx >> 6) * 65 + (idx & 63)] = src[idx];
    __syncthreads();

    #pragma unroll
    for (int idx = tid; idx < 4096; idx += 256) {
        int j = idx >> 6, i = idx & 63;
        dst[(size_t)j * 4096 + r * 64 + i] = s[i * 65 + j];
    }
}

// ============================================================================
// Kernel 1: build W^T[n][k] in fp16.
//   n = j*64 + l, k = i*64 + k2;  Wt[n][k] = sum_r a[r,i,j] * b[r,k2,l]
// Loads at[j] / bt[l] panels fully coalesced (16KB each).
// ============================================================================
__global__ void __launch_bounds__(256) build_wt_kernel()
{
    __shared__ float a_s[64 * 64];  // [r][i]  = a[r,i,j]
    __shared__ float b_s[64 * 64];  // [r][k2] = b[r,k2,l]
    const int n = blockIdx.x;
    const int j = n >> 6, l = n & 63;
    const int tid = threadIdx.x;

    const float* at_j = g_at + (size_t)j * 4096;
    const float* bt_l = g_bt + (size_t)l * 4096;
    #pragma unroll
    for (int idx = tid; idx < 4096; idx += 256) {
        a_s[idx] = at_j[idx];
        b_s[idx] = bt_l[idx];
    }
    __syncthreads();

    const int base = tid * 16;        // 16 consecutive k per thread
    const int i  = base >> 6;
    const int k0 = base & 63;

    float acc[16];
    #pragma unroll
    for (int q = 0; q < 16; q++) acc[q] = 0.0f;

    #pragma unroll 8
    for (int r = 0; r < 64; r++) {
        float av = a_s[r * 64 + i];
        const float4* bp = reinterpret_cast<const float4*>(&b_s[r * 64 + k0]);
        #pragma unroll
        for (int q4 = 0; q4 < 4; q4++) {
            float4 bv = bp[q4];
            acc[4 * q4 + 0] = fmaf(av, bv.x, acc[4 * q4 + 0]);
            acc[4 * q4 + 1] = fmaf(av, bv.y, acc[4 * q4 + 1]);
            acc[4 * q4 + 2] = fmaf(av, bv.z, acc[4 * q4 + 2]);
            acc[4 * q4 + 3] = fmaf(av, bv.w, acc[4 * q4 + 3]);
        }
    }

    __half2* dst = reinterpret_cast<__half2*>(&g_wt[(size_t)n * KDIM + base]);
    #pragma unroll
    for (int q = 0; q < 8; q++)
        dst[q] = __floats2half2_rn(acc[2 * q], acc[2 * q + 1]);
}

// ============================================================================
// Kernel 2: x fp32 -> fp16
// ============================================================================
__global__ void __launch_bounds__(256) convert_x_kernel(const float* __restrict__ x)
{
    const size_t total4 = (size_t)NTOK * KDIM / 4;
    size_t i = (size_t)blockIdx.x * blockDim.x + threadIdx.x;
    const size_t stride = (size_t)gridDim.x * blockDim.x;
    __half2* dst = reinterpret_cast<__half2*>(g_xh);
    for (; i < total4; i += stride) {
        float4 v = reinterpret_cast<const float4*>(x)[i];
        dst[2 * i + 0] = __floats2half2_rn(v.x, v.y);
        dst[2 * i + 1] = __floats2half2_rn(v.z, v.w);
    }
}

// ============================================================================
// Kernel 3: mma.sync fp16 GEMM
//   out[m][n] = sum_k Xh[m][k] * Wt[n][k] + bias[n]
// Tile 256x128x32, 4 cp.async stages, 8 warps (4x2), warp tile 64x64.
// All 16 ldmatrix for the kb issued up front (ILP), then cp.async prefetch,
// then 64 MMAs.
// ============================================================================
static constexpr int BM = 256, BN = 128, BK = 32;
static constexpr int STAGES = 4;
static constexpr int A_STAGE = BM * BK * 2;   // 16384 B
static constexpr int B_STAGE = BN * BK * 2;   //  8192 B
static constexpr int GEMM_SMEM = STAGES * (A_STAGE + B_STAGE);  // 98304 B

__global__ void __launch_bounds__(256, 1) kron_gemm_kernel(
    float* __restrict__ out, const float* __restrict__ bias)
{
    extern __shared__ char smem[];
    const uint32_t smA = smem_to_u32(smem);
    const uint32_t smB = smA + STAGES * A_STAGE;

    const int tid  = threadIdx.x;
    const int wid  = tid >> 5;
    const int lane = tid & 31;
    const int wm   = wid & 3;   // 0..3 -> M
    const int wn   = wid >> 2;  // 0..1 -> N
    const int mBase = blockIdx.y * BM;
    const int nBase = blockIdx.x * BN;

    const __half* Ag = g_xh + (size_t)mBase * KDIM;
    const __half* Bg = g_wt + (size_t)nBase * KDIM;

    const int a_row0 = tid >> 2;
    const int a_c    = tid & 3;

    auto load_stage = [&](int kb, int slot) {
        const __half* Ak = Ag + kb * BK;
        const __half* Bk = Bg + kb * BK;
        uint32_t sA = smA + slot * A_STAGE;
        uint32_t sB = smB + slot * B_STAGE;
        #pragma unroll
        for (int it = 0; it < 4; it++) {
            int row = a_row0 + it * 64;
            CP_ASYNC16(sA + swz(row, a_c), Ak + (size_t)row * KDIM + a_c * 8);
        }
        #pragma unroll
        for (int it = 0; it < 2; it++) {
            int row = a_row0 + it * 64;
            CP_ASYNC16(sB + swz(row, a_c), Bk + (size_t)row * KDIM + a_c * 8);
        }
        CP_COMMIT();
    };

    #pragma unroll
    for (int s = 0; s < STAGES - 1; s++) load_stage(s, s);

    float acc[4][8][4] = {};

    const int lm_row = lane & 15;     // row within 16-row tile
    const int lm_hi  = lane >> 4;     // 0/1 -> which k8 chunk

    const int KITERS = KDIM / BK;     // 128
    #pragma unroll 1
    for (int kb = 0; kb < KITERS; kb++) {
        CP_WAIT(STAGES - 2);
        __syncthreads();

        const int slot = kb & (STAGES - 1);
        const uint32_t sA = smA + slot * A_STAGE;
        const uint32_t sB = smB + slot * B_STAGE;

        // Issue ALL fragment loads for both k16 steps first (maximize MLP).
        uint32_t afrag[2][4][4];
        uint32_t bfrag[2][4][4];
        #pragma unroll
        for (int s = 0; s < 2; s++) {
            const int c = s * 2 + lm_hi;
            #pragma unroll
            for (int mi = 0; mi < 4; mi++)
                ldmx4(afrag[s][mi], sA + swz(wm * 64 + mi * 16 + lm_row, c));
            #pragma unroll
            for (int ni = 0; ni < 4; ni++)
                ldmx4(bfrag[s][ni], sB + swz(wn * 64 + ni * 16 + lm_row, c));
        }

        // Prefetch next stage while ldmatrix results land.
        if (kb + STAGES - 1 < KITERS)
            load_stage(kb + STAGES - 1, (kb + STAGES - 1) & (STAGES - 1));
        else
            CP_COMMIT();   // keep group counting consistent

        #pragma unroll
        for (int s = 0; s < 2; s++) {
            #pragma unroll
            for (int mi = 0; mi < 4; mi++) {
                #pragma unroll
                for (int nj = 0; nj < 8; nj++) {
                    const uint32_t* bg = bfrag[s][nj >> 1];
                    uint32_t b0 = (nj & 1) ? bg[1] : bg[0];
                    uint32_t b1 = (nj & 1) ? bg[3] : bg[2];
                    mma16816(acc[mi][nj], afrag[s][mi], b0, b1);
                }
            }
        }
    }

    // Epilogue: bias hoisted; D frag: thread t -> rows (t/4, t/4+8), cols 2*(t%4)
    const int gr = lane >> 2;
    const int gc = (lane & 3) * 2;
    float bv[8][2];
    #pragma unroll
    for (int nj = 0; nj < 8; nj++) {
        const int n0 = nBase + wn * 64 + nj * 8 + gc;
        bv[nj][0] = __ldg(&bias[n0]);
        bv[nj][1] = __ldg(&bias[n0 + 1]);
    }
    #pragma unroll
    for (int mi = 0; mi < 4; mi++) {
        const int m0 = mBase + wm * 64 + mi * 16 + gr;
        float* r0p = out + (size_t)m0 * NDIM;
        float* r1p = out + (size_t)(m0 + 8) * NDIM;
        #pragma unroll
        for (int nj = 0; nj < 8; nj++) {
            const int n0 = nBase + wn * 64 + nj * 8 + gc;
            float2 v0 = make_float2(acc[mi][nj][0] + bv[nj][0],
                                    acc[mi][nj][1] + bv[nj][1]);
            float2 v1 = make_float2(acc[mi][nj][2] + bv[nj][0],
                                    acc[mi][nj][3] + bv[nj][1]);
            *reinterpret_cast<float2*>(r0p + n0) = v0;
            *reinterpret_cast<float2*>(r1p + n0) = v1;
        }
    }
}

// ============================================================================
// kernel_launch
// Inputs: x (8192*4096 f32), a (64^3 f32), b (64^3 f32), bias (4096 f32)
// Output: 8192*4096 f32
// ============================================================================
extern "C" void kernel_launch(void* const* d_in, const int* in_sizes, int n_in,
                              void* d_out, int out_size)
{
    const float* x    = (const float*)d_in[0];
    const float* a    = (const float*)d_in[1];
    const float* b    = (const float*)d_in[2];
    const float* bias = (const float*)d_in[3];
    float* out = (float*)d_out;

    static bool attr_set = false;
    if (!attr_set) {
        cudaFuncSetAttribute(kron_gemm_kernel,
                             cudaFuncAttributeMaxDynamicSharedMemorySize,
                             GEMM_SMEM);
        attr_set = true;
    }

    // 0. Transpose a, b into coalesced-read layouts
    transpose_ab_kernel<<<128, 256>>>(a, b);

    // 1. Materialize W^T in fp16 (coalesced panel loads)
    build_wt_kernel<<<NDIM, 256>>>();

    // 2. Convert x to fp16
    convert_x_kernel<<<2048, 256>>>(x);

    // 3. Pipelined mma.sync fp16 GEMM with fused bias epilogue
    dim3 grid(NDIM / BN, NTOK / BM);   // (32, 32)
    kron_gemm_kernel<<<grid, 256, GEMM_SMEM>>>(out, bias);
}

// round 4
// speedup vs baseline: 1.6420x; 1.0657x over previous
#include <cuda_runtime.h>
#include <cuda_fp16.h>
#include <cstdint>

// ============================================================================
// Problem dims
// ============================================================================
static constexpr int NTOK = 8192;   // tokens (M)
static constexpr int KDIM = 4096;   // input dim  (a1*b1)
static constexpr int NDIM = 4096;   // output dim (a2*b2)

// Scratch (allocation-free rule: __device__ globals)
__device__ __half g_wt[(size_t)NDIM * KDIM];  // W^T: [n][k] fp16
__device__ __half g_xh[(size_t)NTOK * KDIM];  // x:   [m][k] fp16
__device__ float  g_at[64 * 64 * 64];         // at[j][r][i] = a[r,i,j]
__device__ float  g_bt[64 * 64 * 64];         // bt[l][r][k2] = b[r,k2,l]

// ============================================================================
// PTX helpers (sm_103 baseline only — NO tcgen05 / 'a' features)
// ============================================================================
__device__ __forceinline__ uint32_t smem_to_u32(const void* smem_ptr) {
    uint32_t addr;
    asm("{ .reg .u64 tmp; cvta.to.shared.u64 tmp, %1; cvt.u32.u64 %0, tmp; }"
        : "=r"(addr) : "l"(smem_ptr));
    return addr;
}

#define CP_ASYNC16(smem_u32, gptr) \
    asm volatile("cp.async.cg.shared.global [%0], [%1], 16;\n" \
                 :: "r"(smem_u32), "l"(gptr))
#define CP_COMMIT() asm volatile("cp.async.commit_group;\n" ::: "memory")
#define CP_WAIT(n)  asm volatile("cp.async.wait_group %0;\n" :: "n"(n) : "memory")

__device__ __forceinline__ void ldmx4(uint32_t* r, uint32_t addr) {
    asm volatile("ldmatrix.sync.aligned.m8n8.x4.shared.b16 {%0,%1,%2,%3}, [%4];"
                 : "=r"(r[0]), "=r"(r[1]), "=r"(r[2]), "=r"(r[3])
                 : "r"(addr));
}

__device__ __forceinline__ void mma16816(float* d, const uint32_t* a,
                                         uint32_t b0, uint32_t b1) {
    asm volatile(
        "mma.sync.aligned.m16n8k16.row.col.f32.f16.f16.f32 "
        "{%0,%1,%2,%3}, {%4,%5,%6,%7}, {%8,%9}, {%0,%1,%2,%3};"
        : "+f"(d[0]), "+f"(d[1]), "+f"(d[2]), "+f"(d[3])
        : "r"(a[0]), "r"(a[1]), "r"(a[2]), "r"(a[3]), "r"(b0), "r"(b1));
}

// 64B rows (32 halves), 4 x 16B chunks, swizzle chunk ^= (row>>1)&3
// -> conflict-free for both cp.async 16B stores and ldmatrix reads.
__device__ __forceinline__ uint32_t swz(uint32_t row, uint32_t c) {
    return row * 64u + ((c ^ ((row >> 1) & 3u)) * 16u);
}

// ============================================================================
// Kernel 0: transpose a -> at[j][r][i], b -> bt[l][r][k2]
// ============================================================================
__global__ void __launch_bounds__(256) transpose_ab_kernel(
    const float* __restrict__ a, const float* __restrict__ b)
{
    __shared__ float s[64 * 65];
    const int r = blockIdx.x & 63;
    const bool isA = blockIdx.x < 64;
    const float* src = (isA ? a : b) + (size_t)r * 4096;
    float* dst = isA ? g_at : g_bt;
    const int tid = threadIdx.x;

    #pragma unroll
    for (int idx = tid; idx < 4096; idx += 256)
        s[(idx >> 6) * 65 + (idx & 63)] = src[idx];
    __syncthreads();

    #pragma unroll
    for (int idx = tid; idx < 4096; idx += 256) {
        int j = idx >> 6, i = idx & 63;
        dst[(size_t)j * 4096 + r * 64 + i] = s[i * 65 + j];
    }
}

// ============================================================================
// Kernel 1: build W^T[n][k] in fp16 (coalesced panel loads).
// ============================================================================
__global__ void __launch_bounds__(256) build_wt_kernel()
{
    __shared__ float a_s[64 * 64];  // [r][i]  = a[r,i,j]
    __shared__ float b_s[64 * 64];  // [r][k2] = b[r,k2,l]
    const int n = blockIdx.x;
    const int j = n >> 6, l = n & 63;
    const int tid = threadIdx.x;

    const float* at_j = g_at + (size_t)j * 4096;
    const float* bt_l = g_bt + (size_t)l * 4096;
    #pragma unroll
    for (int idx = tid; idx < 4096; idx += 256) {
        a_s[idx] = at_j[idx];
        b_s[idx] = bt_l[idx];
    }
    __syncthreads();

    const int base = tid * 16;
    const int i  = base >> 6;
    const int k0 = base & 63;

    float acc[16];
    #pragma unroll
    for (int q = 0; q < 16; q++) acc[q] = 0.0f;

    #pragma unroll 8
    for (int r = 0; r < 64; r++) {
        float av = a_s[r * 64 + i];
        const float4* bp = reinterpret_cast<const float4*>(&b_s[r * 64 + k0]);
        #pragma unroll
        for (int q4 = 0; q4 < 4; q4++) {
            float4 bv = bp[q4];
            acc[4 * q4 + 0] = fmaf(av, bv.x, acc[4 * q4 + 0]);
            acc[4 * q4 + 1] = fmaf(av, bv.y, acc[4 * q4 + 1]);
            acc[4 * q4 + 2] = fmaf(av, bv.z, acc[4 * q4 + 2]);
            acc[4 * q4 + 3] = fmaf(av, bv.w, acc[4 * q4 + 3]);
        }
    }

    __half2* dst = reinterpret_cast<__half2*>(&g_wt[(size_t)n * KDIM + base]);
    #pragma unroll
    for (int q = 0; q < 8; q++)
        dst[q] = __floats2half2_rn(acc[2 * q], acc[2 * q + 1]);
}

// ============================================================================
// Kernel 2: x fp32 -> fp16
// ============================================================================
__global__ void __launch_bounds__(256) convert_x_kernel(const float* __restrict__ x)
{
    const size_t total4 = (size_t)NTOK * KDIM / 4;
    size_t i = (size_t)blockIdx.x * blockDim.x + threadIdx.x;
    const size_t stride = (size_t)gridDim.x * blockDim.x;
    __half2* dst = reinterpret_cast<__half2*>(g_xh);
    for (; i < total4; i += stride) {
        float4 v = reinterpret_cast<const float4*>(x)[i];
        dst[2 * i + 0] = __floats2half2_rn(v.x, v.y);
        dst[2 * i + 1] = __floats2half2_rn(v.z, v.w);
    }
}

// ============================================================================
// Kernel 3: mma.sync fp16 GEMM
//   out[m][n] = sum_k Xh[m][k] * Wt[n][k] + bias[n]
// Tile 128x128x32, 4 cp.async stages, 8 warps (4x2), warp tile 32x64.
// __launch_bounds__(256,2) -> <=128 regs -> 2 CTAs/SM -> 4 warps/SMSP.
// ============================================================================
static constexpr int BM = 128, BN = 128, BK = 32;
static constexpr int STAGES = 4;
static constexpr int A_STAGE = BM * BK * 2;   // 8192 B
static constexpr int B_STAGE = BN * BK * 2;   // 8192 B
static constexpr int GEMM_SMEM = STAGES * (A_STAGE + B_STAGE);  // 65536 B

__global__ void __launch_bounds__(256, 2) kron_gemm_kernel(
    float* __restrict__ out, const float* __restrict__ bias)
{
    extern __shared__ char smem[];
    const uint32_t smA = smem_to_u32(smem);
    const uint32_t smB = smA + STAGES * A_STAGE;

    const int tid  = threadIdx.x;
    const int wid  = tid >> 5;
    const int lane = tid & 31;
    const int wm   = wid & 3;   // 0..3 -> M (32 rows each)
    const int wn   = wid >> 2;  // 0..1 -> N (64 cols each)
    const int mBase = blockIdx.y * BM;
    const int nBase = blockIdx.x * BN;

    // cp.async coordinates: 512 chunks/tile/operand? A: 128 rows x 4 chunks
    // = 512 chunks, 256 thr -> 2 per thread; same for B.
    const int a_row0 = tid >> 2;       // 0..63, +64 for second half
    const int a_c    = tid & 3;

    // Running global pointers (avoid per-iter 64-bit address math)
    const __half* Aptr = g_xh + (size_t)mBase * KDIM + (size_t)a_row0 * KDIM + a_c * 8;
    const __half* Bptr = g_wt + (size_t)nBase * KDIM + (size_t)a_row0 * KDIM + a_c * 8;
    const size_t rowHalf = (size_t)64 * KDIM;

    // Smem store offsets (loop-invariant)
    const uint32_t stA0 = swz((uint32_t)a_row0,      (uint32_t)a_c);
    const uint32_t stA1 = swz((uint32_t)a_row0 + 64, (uint32_t)a_c);

    auto load_stage = [&](const __half* Ak, const __half* Bk, int slot) {
        uint32_t sA = smA + slot * A_STAGE;
        uint32_t sB = smB + slot * B_STAGE;
        CP_ASYNC16(sA + stA0, Ak);
        CP_ASYNC16(sA + stA1, Ak + rowHalf);
        CP_ASYNC16(sB + stA0, Bk);
        CP_ASYNC16(sB + stA1, Bk + rowHalf);
        CP_COMMIT();
    };

    #pragma unroll
    for (int s = 0; s < STAGES - 1; s++)
        load_stage(Aptr + s * BK, Bptr + s * BK, s);

    float acc[2][8][4] = {};

    const int lm_row = lane & 15;
    const int lm_hi  = lane >> 4;

    // ldmatrix smem offsets (loop-invariant, slot-relative)
    uint32_t ofA[2][2], ofB[2][4];
    #pragma unroll
    for (int s = 0; s < 2; s++) {
        const int c = s * 2 + lm_hi;
        #pragma unroll
        for (int mi = 0; mi < 2; mi++)
            ofA[s][mi] = swz((uint32_t)(wm * 32 + mi * 16 + lm_row), (uint32_t)c);
        #pragma unroll
        for (int ni = 0; ni < 4; ni++)
            ofB[s][ni] = swz((uint32_t)(wn * 64 + ni * 16 + lm_row), (uint32_t)c);
    }

    const int KITERS = KDIM / BK;     // 128
    #pragma unroll 1
    for (int kb = 0; kb < KITERS; kb++) {
        CP_WAIT(STAGES - 2);
        __syncthreads();

        const int slot = kb & (STAGES - 1);
        const uint32_t sA = smA + slot * A_STAGE;
        const uint32_t sB = smB + slot * B_STAGE;

        // All fragment loads first (max MLP)
        uint32_t afrag[2][2][4];
        uint32_t bfrag[2][4][4];
        #pragma unroll
        for (int s = 0; s < 2; s++) {
            #pragma unroll
            for (int mi = 0; mi < 2; mi++) ldmx4(afrag[s][mi], sA + ofA[s][mi]);
            #pragma unroll
            for (int ni = 0; ni < 4; ni++) ldmx4(bfrag[s][ni], sB + ofB[s][ni]);
        }

        // Prefetch next stage while ldmatrix results land
        const int kn = kb + STAGES - 1;
        if (kn < KITERS)
            load_stage(Aptr + kn * BK, Bptr + kn * BK, kn & (STAGES - 1));
        else
            CP_COMMIT();

        #pragma unroll
        for (int s = 0; s < 2; s++) {
            #pragma unroll
            for (int mi = 0; mi < 2; mi++) {
                #pragma unroll
                for (int nj = 0; nj < 8; nj++) {
                    const uint32_t* bg = bfrag[s][nj >> 1];
                    uint32_t b0 = (nj & 1) ? bg[1] : bg[0];
                    uint32_t b1 = (nj & 1) ? bg[3] : bg[2];
                    mma16816(acc[mi][nj], afrag[s][mi], b0, b1);
                }
            }
        }
    }

    // Epilogue
    const int gr = lane >> 2;
    const int gc = (lane & 3) * 2;
    float bv[8][2];
    #pragma unroll
    for (int nj = 0; nj < 8; nj++) {
        const int n0 = nBase + wn * 64 + nj * 8 + gc;
        bv[nj][0] = __ldg(&bias[n0]);
        bv[nj][1] = __ldg(&bias[n0 + 1]);
    }
    #pragma unroll
    for (int mi = 0; mi < 2; mi++) {
        const int m0 = mBase + wm * 32 + mi * 16 + gr;
        float* r0p = out + (size_t)m0 * NDIM;
        float* r1p = out + (size_t)(m0 + 8) * NDIM;
        #pragma unroll
        for (int nj = 0; nj < 8; nj++) {
            const int n0 = nBase + wn * 64 + nj * 8 + gc;
            float2 v0 = make_float2(acc[mi][nj][0] + bv[nj][0],
                                    acc[mi][nj][1] + bv[nj][1]);
            float2 v1 = make_float2(acc[mi][nj][2] + bv[nj][0],
                                    acc[mi][nj][3] + bv[nj][1]);
            *reinterpret_cast<float2*>(r0p + n0) = v0;
            *reinterpret_cast<float2*>(r1p + n0) = v1;
        }
    }
}

// ============================================================================
// kernel_launch
// ============================================================================
extern "C" void kernel_launch(void* const* d_in, const int* in_sizes, int n_in,
                              void* d_out, int out_size)
{
    const float* x    = (const float*)d_in[0];
    const float* a    = (const float*)d_in[1];
    const float* b    = (const float*)d_in[2];
    const float* bias = (const float*)d_in[3];
    float* out = (float*)d_out;

    static bool attr_set = false;
    if (!attr_set) {
        cudaFuncSetAttribute(kron_gemm_kernel,
                             cudaFuncAttributeMaxDynamicSharedMemorySize,
                             GEMM_SMEM);
        attr_set = true;
    }

    // 0. Transpose a, b into coalesced-read layouts
    transpose_ab_kernel<<<128, 256>>>(a, b);

    // 1. Materialize W^T in fp16
    build_wt_kernel<<<NDIM, 256>>>();

    // 2. Convert x to fp16
    convert_x_kernel<<<2048, 256>>>(x);

    // 3. Pipelined mma.sync fp16 GEMM with fused bias epilogue
    dim3 grid(NDIM / BN, NTOK / BM);   // (32, 64)
    kron_gemm_kernel<<<grid, 256, GEMM_SMEM>>>(out, bias);
}

// round 5
// speedup vs baseline: 1.9551x; 1.1907x over previous
#include <cuda_runtime.h>
#include <cuda_fp16.h>
#include <cstdint>

// ============================================================================
// Problem dims
// ============================================================================
static constexpr int NTOK = 8192;   // tokens (M)
static constexpr int KDIM = 4096;   // input dim  (a1*b1)
static constexpr int NDIM = 4096;   // output dim (a2*b2)

// Scratch (allocation-free rule: __device__ globals)
__device__ __half g_wt[(size_t)NDIM * KDIM];  // W^T: [n][k] fp16
__device__ __half g_xh[(size_t)NTOK * KDIM];  // x:   [m][k] fp16
__device__ float  g_at[64 * 64 * 64];         // at[j][r][i] = a[r,i,j]
__device__ float  g_bt[64 * 64 * 64];         // bt[l][r][k2] = b[r,k2,l]

// ============================================================================
// PTX helpers (sm_103 baseline only — NO tcgen05 / 'a' features)
// ============================================================================
__device__ __forceinline__ uint32_t smem_to_u32(const void* smem_ptr) {
    uint32_t addr;
    asm("{ .reg .u64 tmp; cvta.to.shared.u64 tmp, %1; cvt.u32.u64 %0, tmp; }"
        : "=r"(addr) : "l"(smem_ptr));
    return addr;
}

#define CP_ASYNC16(smem_u32, gptr) \
    asm volatile("cp.async.cg.shared.global [%0], [%1], 16;\n" \
                 :: "r"(smem_u32), "l"(gptr))
#define CP_COMMIT() asm volatile("cp.async.commit_group;\n" ::: "memory")
#define CP_WAIT(n)  asm volatile("cp.async.wait_group %0;\n" :: "n"(n) : "memory")

__device__ __forceinline__ void ldmx4(uint32_t* r, uint32_t addr) {
    asm volatile("ldmatrix.sync.aligned.m8n8.x4.shared.b16 {%0,%1,%2,%3}, [%4];"
                 : "=r"(r[0]), "=r"(r[1]), "=r"(r[2]), "=r"(r[3])
                 : "r"(addr));
}

__device__ __forceinline__ void mma16816(float* d, const uint32_t* a,
                                         uint32_t b0, uint32_t b1) {
    asm volatile(
        "mma.sync.aligned.m16n8k16.row.col.f32.f16.f16.f32 "
        "{%0,%1,%2,%3}, {%4,%5,%6,%7}, {%8,%9}, {%0,%1,%2,%3};"
        : "+f"(d[0]), "+f"(d[1]), "+f"(d[2]), "+f"(d[3])
        : "r"(a[0]), "r"(a[1]), "r"(a[2]), "r"(a[3]), "r"(b0), "r"(b1));
}

// 128B rows (64 halves = BK), 8 x 16B chunks.
// off(row, c) = row*128 + ((c ^ (row&7)) << 4)
// -> per-phase conflict-free for cp.async stores and ldmatrix reads.
// Key property: off(row, c) = off(row, 0) ^ (c << 4).
__device__ __forceinline__ uint32_t swz(uint32_t row, uint32_t c) {
    return row * 128u + (((c ^ (row & 7u)) & 7u) << 4);
}

// ============================================================================
// Kernel 0: transpose a -> at[j][r][i], b -> bt[l][r][k2]
// ============================================================================
__global__ void __launch_bounds__(256) transpose_ab_kernel(
    const float* __restrict__ a, const float* __restrict__ b)
{
    __shared__ float s[64 * 65];
    const int r = blockIdx.x & 63;
    const bool isA = blockIdx.x < 64;
    const float* src = (isA ? a : b) + (size_t)r * 4096;
    float* dst = isA ? g_at : g_bt;
    const int tid = threadIdx.x;

    #pragma unroll
    for (int idx = tid; idx < 4096; idx += 256)
        s[(idx >> 6) * 65 + (idx & 63)] = src[idx];
    __syncthreads();

    #pragma unroll
    for (int idx = tid; idx < 4096; idx += 256) {
        int j = idx >> 6, i = idx & 63;
        dst[(size_t)j * 4096 + r * 64 + i] = s[i * 65 + j];
    }
}

// ============================================================================
// Kernel 1: build W^T[n][k] in fp16 (coalesced panel loads, 16B stores).
// ============================================================================
__global__ void __launch_bounds__(256) build_wt_kernel()
{
    __shared__ float a_s[64 * 64];  // [r][i]
    __shared__ float b_s[64 * 64];  // [r][k2]
    const int n = blockIdx.x;
    const int j = n >> 6, l = n & 63;
    const int tid = threadIdx.x;

    const float* at_j = g_at + (size_t)j * 4096;
    const float* bt_l = g_bt + (size_t)l * 4096;
    #pragma unroll
    for (int idx = tid; idx < 4096; idx += 256) {
        a_s[idx] = at_j[idx];
        b_s[idx] = bt_l[idx];
    }
    __syncthreads();

    const int base = tid * 16;
    const int i  = base >> 6;
    const int k0 = base & 63;

    float acc[16];
    #pragma unroll
    for (int q = 0; q < 16; q++) acc[q] = 0.0f;

    #pragma unroll 8
    for (int r = 0; r < 64; r++) {
        float av = a_s[r * 64 + i];
        const float4* bp = reinterpret_cast<const float4*>(&b_s[r * 64 + k0]);
        #pragma unroll
        for (int q4 = 0; q4 < 4; q4++) {
            float4 bv = bp[q4];
            acc[4 * q4 + 0] = fmaf(av, bv.x, acc[4 * q4 + 0]);
            acc[4 * q4 + 1] = fmaf(av, bv.y, acc[4 * q4 + 1]);
            acc[4 * q4 + 2] = fmaf(av, bv.z, acc[4 * q4 + 2]);
            acc[4 * q4 + 3] = fmaf(av, bv.w, acc[4 * q4 + 3]);
        }
    }

    uint4 st[2];
    __half2* h2 = reinterpret_cast<__half2*>(st);
    #pragma unroll
    for (int q = 0; q < 8; q++)
        h2[q] = __floats2half2_rn(acc[2 * q], acc[2 * q + 1]);
    uint4* dst = reinterpret_cast<uint4*>(&g_wt[(size_t)n * KDIM + base]);
    dst[0] = st[0];
    dst[1] = st[1];
}

// ============================================================================
// Kernel 2: x fp32 -> fp16
// ============================================================================
__global__ void __launch_bounds__(256) convert_x_kernel(const float* __restrict__ x)
{
    const size_t total4 = (size_t)NTOK * KDIM / 4;
    size_t i = (size_t)blockIdx.x * blockDim.x + threadIdx.x;
    const size_t stride = (size_t)gridDim.x * blockDim.x;
    __half2* dst = reinterpret_cast<__half2*>(g_xh);
    for (; i < total4; i += stride) {
        float4 v = reinterpret_cast<const float4*>(x)[i];
        dst[2 * i + 0] = __floats2half2_rn(v.x, v.y);
        dst[2 * i + 1] = __floats2half2_rn(v.z, v.w);
    }
}

// ============================================================================
// Kernel 3: mma.sync fp16 GEMM
//   out[m][n] = sum_k Xh[m][k] * Wt[n][k] + bias[n]
// Tile 128x128x64, 3 cp.async stages (96KB), 8 warps (4x2), warp tile 32x64.
// Register-ring software pipeline over the 4 k16 steps per stage.
// __launch_bounds__(256,2) -> 2 CTAs/SM.
// ============================================================================
static constexpr int BM = 128, BN = 128, BK = 64;
static constexpr int STAGES = 3;
static constexpr int A_STAGE = BM * BK * 2;   // 16384 B
static constexpr int B_STAGE = BN * BK * 2;   // 16384 B
static constexpr int GEMM_SMEM = STAGES * (A_STAGE + B_STAGE);  // 98304 B

__global__ void __launch_bounds__(256, 2) kron_gemm_kernel(
    float* __restrict__ out, const float* __restrict__ bias)
{
    extern __shared__ char smem[];
    const uint32_t smA = smem_to_u32(smem);
    const uint32_t smB = smA + STAGES * A_STAGE;

    const int tid  = threadIdx.x;
    const int wid  = tid >> 5;
    const int lane = tid & 31;
    const int wm   = wid & 3;   // 0..3 -> M (32 rows)
    const int wn   = wid >> 2;  // 0..1 -> N (64 cols)
    const int mBase = blockIdx.y * BM;
    const int nBase = blockIdx.x * BN;

    // cp.async: 128 rows x 8 chunks = 1024 chunks per operand; 4 per thread.
    const int c_row0 = tid >> 3;       // 0..31, strided by +32
    const int c_c    = tid & 7;

    const __half* Aptr = g_xh + ((size_t)mBase + c_row0) * KDIM + c_c * 8;
    const __half* Bptr = g_wt + ((size_t)nBase + c_row0) * KDIM + c_c * 8;
    const size_t rowStep = (size_t)32 * KDIM;

    uint32_t stOff[4];
    #pragma unroll
    for (int it = 0; it < 4; it++)
        stOff[it] = swz((uint32_t)(c_row0 + it * 32), (uint32_t)c_c);

    auto load_stage = [&](const __half* Ak, const __half* Bk, int slot) {
        uint32_t sA = smA + slot * A_STAGE;
        uint32_t sB = smB + slot * B_STAGE;
        #pragma unroll
        for (int it = 0; it < 4; it++)
            CP_ASYNC16(sA + stOff[it], Ak + it * rowStep);
        #pragma unroll
        for (int it = 0; it < 4; it++)
            CP_ASYNC16(sB + stOff[it], Bk + it * rowStep);
        CP_COMMIT();
    };

    #pragma unroll
    for (int s = 0; s < STAGES - 1; s++)
        load_stage(Aptr + s * BK, Bptr + s * BK, s);

    float acc[2][8][4] = {};

    const int lm_row = lane & 15;
    const int lm_hi  = lane >> 4;      // 0/1: low/high k8 of the k16 step

    // ldmatrix base offsets at chunk 0; step-s chunk = 2s+lm_hi -> XOR (c<<4)
    uint32_t baseA[2], baseB[4];
    #pragma unroll
    for (int mi = 0; mi < 2; mi++)
        baseA[mi] = swz((uint32_t)(wm * 32 + mi * 16 + lm_row), 0) ^ ((uint32_t)lm_hi << 4);
    #pragma unroll
    for (int ni = 0; ni < 4; ni++)
        baseB[ni] = swz((uint32_t)(wn * 64 + ni * 16 + lm_row), 0) ^ ((uint32_t)lm_hi << 4);

    uint32_t afrag[2][2][4];   // [ring][mi][reg]
    uint32_t bfrag[2][4][4];   // [ring][ni][reg]

    auto load_frags = [&](uint32_t sA, uint32_t sB, int s, int buf) {
        const uint32_t cx = (uint32_t)(2 * s) << 4;   // XOR delta for this step
        #pragma unroll
        for (int mi = 0; mi < 2; mi++) ldmx4(afrag[buf][mi], sA + (baseA[mi] ^ cx));
        #pragma unroll
        for (int ni = 0; ni < 4; ni++) ldmx4(bfrag[buf][ni], sB + (baseB[ni] ^ cx));
    };

    auto do_mmas = [&](int buf) {
        #pragma unroll
        for (int mi = 0; mi < 2; mi++) {
            #pragma unroll
            for (int nj = 0; nj < 8; nj++) {
                const uint32_t* bg = bfrag[buf][nj >> 1];
                uint32_t b0 = (nj & 1) ? bg[1] : bg[0];
                uint32_t b1 = (nj & 1) ? bg[3] : bg[2];
                mma16816(acc[mi][nj], afrag[buf][mi], b0, b1);
            }
        }
    };

    const int KITERS = KDIM / BK;     // 64
    #pragma unroll 1
    for (int kb = 0; kb < KITERS; kb++) {
        CP_WAIT(1);
        __syncthreads();

        int slot = kb;
        if (slot >= STAGES) slot -= STAGES * (slot / STAGES);   // kb % 3
        const uint32_t sA = smA + slot * A_STAGE;
        const uint32_t sB = smB + slot * B_STAGE;

        load_frags(sA, sB, 0, 0);

        // Prefetch stage kb+2 into slot (kb+2)%3 — safe: issued after the
        // barrier, so no warp is still reading that slot.
        const int kn = kb + STAGES - 1;
        if (kn < KITERS) {
            int ns = kn;
            ns -= STAGES * (ns / STAGES);
            load_stage(Aptr + kn * BK, Bptr + kn * BK, ns);
        }

        #pragma unroll
        for (int s = 0; s < 4; s++) {
            if (s < 3) load_frags(sA, sB, s + 1, (s + 1) & 1);
            do_mmas(s & 1);
        }
    }

    // Epilogue
    const int gr = lane >> 2;
    const int gc = (lane & 3) * 2;
    float bv[8][2];
    #pragma unroll
    for (int nj = 0; nj < 8; nj++) {
        const int n0 = nBase + wn * 64 + nj * 8 + gc;
        bv[nj][0] = __ldg(&bias[n0]);
        bv[nj][1] = __ldg(&bias[n0 + 1]);
    }
    #pragma unroll
    for (int mi = 0; mi < 2; mi++) {
        const int m0 = mBase + wm * 32 + mi * 16 + gr;
        float* r0p = out + (size_t)m0 * NDIM;
        float* r1p = out + (size_t)(m0 + 8) * NDIM;
        #pragma unroll
        for (int nj = 0; nj < 8; nj++) {
            const int n0 = nBase + wn * 64 + nj * 8 + gc;
            float2 v0 = make_float2(acc[mi][nj][0] + bv[nj][0],
                                    acc[mi][nj][1] + bv[nj][1]);
            float2 v1 = make_float2(acc[mi][nj][2] + bv[nj][0],
                                    acc[mi][nj][3] + bv[nj][1]);
            *reinterpret_cast<float2*>(r0p + n0) = v0;
            *reinterpret_cast<float2*>(r1p + n0) = v1;
        }
    }
}

// ============================================================================
// kernel_launch
// ============================================================================
extern "C" void kernel_launch(void* const* d_in, const int* in_sizes, int n_in,
                              void* d_out, int out_size)
{
    const float* x    = (const float*)d_in[0];
    const float* a    = (const float*)d_in[1];
    const float* b    = (const float*)d_in[2];
    const float* bias = (const float*)d_in[3];
    float* out = (float*)d_out;

    static bool attr_set = false;
    if (!attr_set) {
        cudaFuncSetAttribute(kron_gemm_kernel,
                             cudaFuncAttributeMaxDynamicSharedMemorySize,
                             GEMM_SMEM);
        attr_set = true;
    }

    // 0. Transpose a, b into coalesced-read layouts
    transpose_ab_kernel<<<128, 256>>>(a, b);

    // 1. Materialize W^T in fp16
    build_wt_kernel<<<NDIM, 256>>>();

    // 2. Convert x to fp16
    convert_x_kernel<<<2048, 256>>>(x);

    // 3. Pipelined mma.sync fp16 GEMM with fused bias epilogue
    dim3 grid(NDIM / BN, NTOK / BM);   // (32, 64)
    kron_gemm_kernel<<<grid, 256, GEMM_SMEM>>>(out, bias);
}

// round 6
// speedup vs baseline: 2.3184x; 1.1858x over previous
#include <cuda_runtime.h>
#include <cuda_fp16.h>
#include <cstdint>

// ============================================================================
// Problem dims
// ============================================================================
static constexpr int NTOK = 8192;   // tokens (M)
static constexpr int KDIM = 4096;   // input dim  (a1*b1)
static constexpr int NDIM = 4096;   // output dim (a2*b2)

// Scratch (allocation-free rule: __device__ globals)
__device__ __half g_wt[(size_t)NDIM * KDIM];  // W^T: [n][k] fp16
__device__ __half g_xh[(size_t)NTOK * KDIM];  // x:   [m][k] fp16
__device__ float  g_at[64 * 64 * 64];         // at[j][r][i] = a[r,i,j]
__device__ float  g_bt[64 * 64 * 64];         // bt[l][r][k2] = b[r,k2,l]

// ============================================================================
// PTX helpers (sm_103 baseline only — NO tcgen05 / 'a' features)
// ============================================================================
__device__ __forceinline__ uint32_t smem_to_u32(const void* smem_ptr) {
    uint32_t addr;
    asm("{ .reg .u64 tmp; cvta.to.shared.u64 tmp, %1; cvt.u32.u64 %0, tmp; }"
        : "=r"(addr) : "l"(smem_ptr));
    return addr;
}

#define CP_ASYNC16(smem_u32, gptr) \
    asm volatile("cp.async.cg.shared.global [%0], [%1], 16;\n" \
                 :: "r"(smem_u32), "l"(gptr))
#define CP_COMMIT() asm volatile("cp.async.commit_group;\n" ::: "memory")
#define CP_WAIT(n)  asm volatile("cp.async.wait_group %0;\n" :: "n"(n) : "memory")

__device__ __forceinline__ void ldmx4(uint32_t* r, uint32_t addr) {
    asm volatile("ldmatrix.sync.aligned.m8n8.x4.shared.b16 {%0,%1,%2,%3}, [%4];"
                 : "=r"(r[0]), "=r"(r[1]), "=r"(r[2]), "=r"(r[3])
                 : "r"(addr));
}

__device__ __forceinline__ void mma16816(float* d, const uint32_t* a,
                                         uint32_t b0, uint32_t b1) {
    asm volatile(
        "mma.sync.aligned.m16n8k16.row.col.f32.f16.f16.f32 "
        "{%0,%1,%2,%3}, {%4,%5,%6,%7}, {%8,%9}, {%0,%1,%2,%3};"
        : "+f"(d[0]), "+f"(d[1]), "+f"(d[2]), "+f"(d[3])
        : "r"(a[0]), "r"(a[1]), "r"(a[2]), "r"(a[3]), "r"(b0), "r"(b1));
}

// 128B rows (64 halves = BK), 8 x 16B chunks.
// off(row, c) = row*128 + ((c ^ (row&7)) << 4)
// Key property: off(row, c) = off(row, 0) ^ (c << 4).
__device__ __forceinline__ uint32_t swz(uint32_t row, uint32_t c) {
    return row * 128u + (((c ^ (row & 7u)) & 7u) << 4);
}

// ============================================================================
// Kernel 0: transpose a -> at[j][r][i], b -> bt[l][r][k2]
// ============================================================================
__global__ void __launch_bounds__(256) transpose_ab_kernel(
    const float* __restrict__ a, const float* __restrict__ b)
{
    __shared__ float s[64 * 65];
    const int r = blockIdx.x & 63;
    const bool isA = blockIdx.x < 64;
    const float* src = (isA ? a : b) + (size_t)r * 4096;
    float* dst = isA ? g_at : g_bt;
    const int tid = threadIdx.x;

    #pragma unroll
    for (int idx = tid; idx < 4096; idx += 256)
        s[(idx >> 6) * 65 + (idx & 63)] = src[idx];
    __syncthreads();

    #pragma unroll
    for (int idx = tid; idx < 4096; idx += 256) {
        int j = idx >> 6, i = idx & 63;
        dst[(size_t)j * 4096 + r * 64 + i] = s[i * 65 + j];
    }
}

// ============================================================================
// Kernel 1: build W^T[n][k] in fp16.
// 4i x 4k register blocking: per r two LDS128 + 16 FFMA (smem traffic /2).
// ============================================================================
__global__ void __launch_bounds__(256) build_wt_kernel()
{
    __shared__ float a_s[64 * 64];  // [r][i]
    __shared__ float b_s[64 * 64];  // [r][k2]
    const int n = blockIdx.x;
    const int j = n >> 6, l = n & 63;
    const int tid = threadIdx.x;

    const float* at_j = g_at + (size_t)j * 4096;
    const float* bt_l = g_bt + (size_t)l * 4096;
    #pragma unroll
    for (int idx = tid; idx < 4096; idx += 256) {
        a_s[idx] = at_j[idx];
        b_s[idx] = bt_l[idx];
    }
    __syncthreads();

    const int i0 = (tid >> 4) * 4;   // 16 i-groups
    const int k0 = (tid & 15) * 4;   // 16 k-groups

    float acc[4][4];
    #pragma unroll
    for (int ii = 0; ii < 4; ii++)
        #pragma unroll
        for (int kk = 0; kk < 4; kk++) acc[ii][kk] = 0.0f;

    #pragma unroll 4
    for (int r = 0; r < 64; r++) {
        float4 a4 = *reinterpret_cast<const float4*>(&a_s[r * 64 + i0]);
        float4 b4 = *reinterpret_cast<const float4*>(&b_s[r * 64 + k0]);
        const float av[4] = {a4.x, a4.y, a4.z, a4.w};
        const float bv[4] = {b4.x, b4.y, b4.z, b4.w};
        #pragma unroll
        for (int ii = 0; ii < 4; ii++)
            #pragma unroll
            for (int kk = 0; kk < 4; kk++)
                acc[ii][kk] = fmaf(av[ii], bv[kk], acc[ii][kk]);
    }

    // Write 4 rows x 4 halves (8B per row chunk)
    #pragma unroll
    for (int ii = 0; ii < 4; ii++) {
        __half2 h0 = __floats2half2_rn(acc[ii][0], acc[ii][1]);
        __half2 h1 = __floats2half2_rn(acc[ii][2], acc[ii][3]);
        uint2 st;
        st.x = *reinterpret_cast<uint32_t*>(&h0);
        st.y = *reinterpret_cast<uint32_t*>(&h1);
        *reinterpret_cast<uint2*>(&g_wt[(size_t)n * KDIM + (i0 + ii) * 64 + k0]) = st;
    }
}

// ============================================================================
// Kernel 2: x fp32 -> fp16
// ============================================================================
__global__ void __launch_bounds__(256) convert_x_kernel(const float* __restrict__ x)
{
    const size_t total4 = (size_t)NTOK * KDIM / 4;
    size_t i = (size_t)blockIdx.x * blockDim.x + threadIdx.x;
    const size_t stride = (size_t)gridDim.x * blockDim.x;
    __half2* dst = reinterpret_cast<__half2*>(g_xh);
    for (; i < total4; i += stride) {
        float4 v = reinterpret_cast<const float4*>(x)[i];
        dst[2 * i + 0] = __floats2half2_rn(v.x, v.y);
        dst[2 * i + 1] = __floats2half2_rn(v.z, v.w);
    }
}

// ============================================================================
// Kernel 3: mma.sync fp16 GEMM
// Tile 128x128x64, 3 cp.async stages (96KB), 8 warps (4x2), warp tile 32x64.
// Register-ring pipeline over the 4 k16 steps; cp.async prefetch interleaved
// between the pipeline steps. __launch_bounds__(256,2) -> 2 CTAs/SM.
// ============================================================================
static constexpr int BM = 128, BN = 128, BK = 64;
static constexpr int STAGES = 3;
static constexpr int A_STAGE = BM * BK * 2;   // 16384 B
static constexpr int B_STAGE = BN * BK * 2;   // 16384 B
static constexpr int GEMM_SMEM = STAGES * (A_STAGE + B_STAGE);  // 98304 B

__global__ void __launch_bounds__(256, 2) kron_gemm_kernel(
    float* __restrict__ out, const float* __restrict__ bias)
{
    extern __shared__ char smem[];
    const uint32_t smA = smem_to_u32(smem);
    const uint32_t smB = smA + STAGES * A_STAGE;

    const int tid  = threadIdx.x;
    const int wid  = tid >> 5;
    const int lane = tid & 31;
    const int wm   = wid & 3;   // 0..3 -> M (32 rows)
    const int wn   = wid >> 2;  // 0..1 -> N (64 cols)
    const int mBase = blockIdx.y * BM;
    const int nBase = blockIdx.x * BN;

    const int c_row0 = tid >> 3;       // 0..31, strided by +32
    const int c_c    = tid & 7;

    const __half* Aptr = g_xh + ((size_t)mBase + c_row0) * KDIM + c_c * 8;
    const __half* Bptr = g_wt + ((size_t)nBase + c_row0) * KDIM + c_c * 8;
    const size_t rowStep = (size_t)32 * KDIM;

    uint32_t stOff[4];
    #pragma unroll
    for (int it = 0; it < 4; it++)
        stOff[it] = swz((uint32_t)(c_row0 + it * 32), (uint32_t)c_c);

    auto load_stage = [&](const __half* Ak, const __half* Bk, int slot) {
        uint32_t sA = smA + slot * A_STAGE;
        uint32_t sB = smB + slot * B_STAGE;
        #pragma unroll
        for (int it = 0; it < 4; it++)
            CP_ASYNC16(sA + stOff[it], Ak + it * rowStep);
        #pragma unroll
        for (int it = 0; it < 4; it++)
            CP_ASYNC16(sB + stOff[it], Bk + it * rowStep);
        CP_COMMIT();
    };

    #pragma unroll
    for (int s = 0; s < STAGES - 1; s++)
        load_stage(Aptr + s * BK, Bptr + s * BK, s);

    float acc[2][8][4] = {};

    const int lm_row = lane & 15;
    const int lm_hi  = lane >> 4;

    uint32_t baseA[2], baseB[4];
    #pragma unroll
    for (int mi = 0; mi < 2; mi++)
        baseA[mi] = swz((uint32_t)(wm * 32 + mi * 16 + lm_row), 0) ^ ((uint32_t)lm_hi << 4);
    #pragma unroll
    for (int ni = 0; ni < 4; ni++)
        baseB[ni] = swz((uint32_t)(wn * 64 + ni * 16 + lm_row), 0) ^ ((uint32_t)lm_hi << 4);

    uint32_t afrag[2][2][4];
    uint32_t bfrag[2][4][4];

    auto load_frags = [&](uint32_t sA, uint32_t sB, int s, int buf) {
        const uint32_t cx = (uint32_t)(2 * s) << 4;
        #pragma unroll
        for (int mi = 0; mi < 2; mi++) ldmx4(afrag[buf][mi], sA + (baseA[mi] ^ cx));
        #pragma unroll
        for (int ni = 0; ni < 4; ni++) ldmx4(bfrag[buf][ni], sB + (baseB[ni] ^ cx));
    };

    auto do_mmas = [&](int buf) {
        #pragma unroll
        for (int mi = 0; mi < 2; mi++) {
            #pragma unroll
            for (int nj = 0; nj < 8; nj++) {
                const uint32_t* bg = bfrag[buf][nj >> 1];
                uint32_t b0 = (nj & 1) ? bg[1] : bg[0];
                uint32_t b1 = (nj & 1) ? bg[3] : bg[2];
                mma16816(acc[mi][nj], afrag[buf][mi], b0, b1);
            }
        }
    };

    const int KITERS = KDIM / BK;     // 64
    int slot = 0, nslot = STAGES - 1;
    #pragma unroll 1
    for (int kb = 0; kb < KITERS; kb++) {
        CP_WAIT(1);
        __syncthreads();

        const uint32_t sA = smA + slot * A_STAGE;
        const uint32_t sB = smB + slot * B_STAGE;

        load_frags(sA, sB, 0, 0);

        const int kn = kb + STAGES - 1;
        const bool pf = (kn < KITERS);
        const __half* Apf = Aptr + kn * BK;
        const __half* Bpf = Bptr + kn * BK;
        const uint32_t pA = smA + nslot * A_STAGE;
        const uint32_t pB = smB + nslot * B_STAGE;

        // Pipeline: frag loads 1 step ahead of MMAs; cp.async spread across steps.
        load_frags(sA, sB, 1, 1);
        if (pf) {
            CP_ASYNC16(pA + stOff[0], Apf);
            CP_ASYNC16(pA + stOff[1], Apf + rowStep);
        }
        do_mmas(0);

        load_frags(sA, sB, 2, 0);
        if (pf) {
            CP_ASYNC16(pA + stOff[2], Apf + 2 * rowStep);
            CP_ASYNC16(pA + stOff[3], Apf + 3 * rowStep);
        }
        do_mmas(1);

        load_frags(sA, sB, 3, 1);
        if (pf) {
            CP_ASYNC16(pB + stOff[0], Bpf);
            CP_ASYNC16(pB + stOff[1], Bpf + rowStep);
        }
        do_mmas(0);

        if (pf) {
            CP_ASYNC16(pB + stOff[2], Bpf + 2 * rowStep);
            CP_ASYNC16(pB + stOff[3], Bpf + 3 * rowStep);
        }
        CP_COMMIT();
        do_mmas(1);

        slot = (slot == STAGES - 1) ? 0 : slot + 1;
        nslot = (nslot == STAGES - 1) ? 0 : nslot + 1;
    }

    // Epilogue
    const int gr = lane >> 2;
    const int gc = (lane & 3) * 2;
    float bv[8][2];
    #pragma unroll
    for (int nj = 0; nj < 8; nj++) {
        const int n0 = nBase + wn * 64 + nj * 8 + gc;
        bv[nj][0] = __ldg(&bias[n0]);
        bv[nj][1] = __ldg(&bias[n0 + 1]);
    }
    #pragma unroll
    for (int mi = 0; mi < 2; mi++) {
        const int m0 = mBase + wm * 32 + mi * 16 + gr;
        float* r0p = out + (size_t)m0 * NDIM;
        float* r1p = out + (size_t)(m0 + 8) * NDIM;
        #pragma unroll
        for (int nj = 0; nj < 8; nj++) {
            const int n0 = nBase + wn * 64 + nj * 8 + gc;
            float2 v0 = make_float2(acc[mi][nj][0] + bv[nj][0],
                                    acc[mi][nj][1] + bv[nj][1]);
            float2 v1 = make_float2(acc[mi][nj][2] + bv[nj][0],
                                    acc[mi][nj][3] + bv[nj][1]);
            *reinterpret_cast<float2*>(r0p + n0) = v0;
            *reinterpret_cast<float2*>(r1p + n0) = v1;
        }
    }
}

// ============================================================================
// kernel_launch
// ============================================================================
extern "C" void kernel_launch(void* const* d_in, const int* in_sizes, int n_in,
                              void* d_out, int out_size)
{
    const float* x    = (const float*)d_in[0];
    const float* a    = (const float*)d_in[1];
    const float* b    = (const float*)d_in[2];
    const float* bias = (const float*)d_in[3];
    float* out = (float*)d_out;

    static bool attr_set = false;
    if (!attr_set) {
        cudaFuncSetAttribute(kron_gemm_kernel,
                             cudaFuncAttributeMaxDynamicSharedMemorySize,
                             GEMM_SMEM);
        attr_set = true;
    }

    // 0. Transpose a, b into coalesced-read layouts
    transpose_ab_kernel<<<128, 256>>>(a, b);

    // 1. Materialize W^T in fp16 (register-blocked)
    build_wt_kernel<<<NDIM, 256>>>();

    // 2. Convert x to fp16
    convert_x_kernel<<<2048, 256>>>(x);

    // 3. Pipelined mma.sync fp16 GEMM with fused bias epilogue
    dim3 grid(NDIM / BN, NTOK / BM);   // (32, 64)
    kron_gemm_kernel<<<grid, 256, GEMM_SMEM>>>(out, bias);
}

// round 7
// speedup vs baseline: 2.3412x; 1.0099x over previous
#include <cuda_runtime.h>
#include <cuda_fp16.h>
#include <cstdint>

// ============================================================================
// Problem dims
// ============================================================================
static constexpr int NTOK = 8192;   // tokens (M)
static constexpr int KDIM = 4096;   // input dim  (a1*b1)
static constexpr int NDIM = 4096;   // output dim (a2*b2)

// Scratch (allocation-free rule: __device__ globals)
__device__ __half g_wt[(size_t)NDIM * KDIM];  // W^T: [n][k] fp16
__device__ __half g_xh[(size_t)NTOK * KDIM];  // x:   [m][k] fp16
__device__ float  g_at[64 * 64 * 64];         // at[j][r][i] = a[r,i,j]
__device__ float  g_bt[64 * 64 * 64];         // bt[l][r][k2] = b[r,k2,l]

// ============================================================================
// PTX helpers (sm_103 baseline only — NO tcgen05 / 'a' features)
// ============================================================================
__device__ __forceinline__ uint32_t smem_to_u32(const void* smem_ptr) {
    uint32_t addr;
    asm("{ .reg .u64 tmp; cvta.to.shared.u64 tmp, %1; cvt.u32.u64 %0, tmp; }"
        : "=r"(addr) : "l"(smem_ptr));
    return addr;
}

#define CP_ASYNC16(smem_u32, gptr) \
    asm volatile("cp.async.cg.shared.global [%0], [%1], 16;\n" \
                 :: "r"(smem_u32), "l"(gptr))
#define CP_COMMIT() asm volatile("cp.async.commit_group;\n" ::: "memory")
#define CP_WAIT(n)  asm volatile("cp.async.wait_group %0;\n" :: "n"(n) : "memory")

__device__ __forceinline__ void ldmx4(uint32_t* r, uint32_t addr) {
    asm volatile("ldmatrix.sync.aligned.m8n8.x4.shared.b16 {%0,%1,%2,%3}, [%4];"
                 : "=r"(r[0]), "=r"(r[1]), "=r"(r[2]), "=r"(r[3])
                 : "r"(addr));
}

__device__ __forceinline__ void mma16816(float* d, const uint32_t* a,
                                         uint32_t b0, uint32_t b1) {
    asm volatile(
        "mma.sync.aligned.m16n8k16.row.col.f32.f16.f16.f32 "
        "{%0,%1,%2,%3}, {%4,%5,%6,%7}, {%8,%9}, {%0,%1,%2,%3};"
        : "+f"(d[0]), "+f"(d[1]), "+f"(d[2]), "+f"(d[3])
        : "r"(a[0]), "r"(a[1]), "r"(a[2]), "r"(a[3]), "r"(b0), "r"(b1));
}

// 128B rows (64 halves = BK), 8 x 16B chunks.
// off(row, c) = row*128 + ((c ^ (row&7)) << 4)
// Key property: off(row, c) = off(row, 0) ^ (c << 4).
__device__ __forceinline__ uint32_t swz(uint32_t row, uint32_t c) {
    return row * 128u + (((c ^ (row & 7u)) & 7u) << 4);
}

// ============================================================================
// Kernel 0: transpose a -> at[j][r][i], b -> bt[l][r][k2]
// ============================================================================
__global__ void __launch_bounds__(256) transpose_ab_kernel(
    const float* __restrict__ a, const float* __restrict__ b)
{
    __shared__ float s[64 * 65];
    const int r = blockIdx.x & 63;
    const bool isA = blockIdx.x < 64;
    const float* src = (isA ? a : b) + (size_t)r * 4096;
    float* dst = isA ? g_at : g_bt;
    const int tid = threadIdx.x;

    #pragma unroll
    for (int idx = tid; idx < 4096; idx += 256)
        s[(idx >> 6) * 65 + (idx & 63)] = src[idx];
    __syncthreads();

    #pragma unroll
    for (int idx = tid; idx < 4096; idx += 256) {
        int j = idx >> 6, i = idx & 63;
        dst[(size_t)j * 4096 + r * 64 + i] = s[i * 65 + j];
    }
}

// ============================================================================
// Kernel 1: build W^T[n][k] in fp16 (4x4 register blocking).
// ============================================================================
__global__ void __launch_bounds__(256) build_wt_kernel()
{
    __shared__ float a_s[64 * 64];  // [r][i]
    __shared__ float b_s[64 * 64];  // [r][k2]
    const int n = blockIdx.x;
    const int j = n >> 6, l = n & 63;
    const int tid = threadIdx.x;

    const float* at_j = g_at + (size_t)j * 4096;
    const float* bt_l = g_bt + (size_t)l * 4096;
    #pragma unroll
    for (int idx = tid; idx < 4096; idx += 256) {
        a_s[idx] = at_j[idx];
        b_s[idx] = bt_l[idx];
    }
    __syncthreads();

    const int i0 = (tid >> 4) * 4;
    const int k0 = (tid & 15) * 4;

    float acc[4][4];
    #pragma unroll
    for (int ii = 0; ii < 4; ii++)
        #pragma unroll
        for (int kk = 0; kk < 4; kk++) acc[ii][kk] = 0.0f;

    #pragma unroll 4
    for (int r = 0; r < 64; r++) {
        float4 a4 = *reinterpret_cast<const float4*>(&a_s[r * 64 + i0]);
        float4 b4 = *reinterpret_cast<const float4*>(&b_s[r * 64 + k0]);
        const float av[4] = {a4.x, a4.y, a4.z, a4.w};
        const float bv[4] = {b4.x, b4.y, b4.z, b4.w};
        #pragma unroll
        for (int ii = 0; ii < 4; ii++)
            #pragma unroll
            for (int kk = 0; kk < 4; kk++)
                acc[ii][kk] = fmaf(av[ii], bv[kk], acc[ii][kk]);
    }

    #pragma unroll
    for (int ii = 0; ii < 4; ii++) {
        __half2 h0 = __floats2half2_rn(acc[ii][0], acc[ii][1]);
        __half2 h1 = __floats2half2_rn(acc[ii][2], acc[ii][3]);
        uint2 st;
        st.x = *reinterpret_cast<uint32_t*>(&h0);
        st.y = *reinterpret_cast<uint32_t*>(&h1);
        *reinterpret_cast<uint2*>(&g_wt[(size_t)n * KDIM + (i0 + ii) * 64 + k0]) = st;
    }
}

// ============================================================================
// Kernel 2: x fp32 -> fp16
// ============================================================================
__global__ void __launch_bounds__(256) convert_x_kernel(const float* __restrict__ x)
{
    const size_t total4 = (size_t)NTOK * KDIM / 4;
    size_t i = (size_t)blockIdx.x * blockDim.x + threadIdx.x;
    const size_t stride = (size_t)gridDim.x * blockDim.x;
    __half2* dst = reinterpret_cast<__half2*>(g_xh);
    for (; i < total4; i += stride) {
        float4 v = reinterpret_cast<const float4*>(x)[i];
        dst[2 * i + 0] = __floats2half2_rn(v.x, v.y);
        dst[2 * i + 1] = __floats2half2_rn(v.z, v.w);
    }
}

// ============================================================================
// Kernel 3: mma.sync fp16 GEMM
// Tile 128x128x64, 3 cp.async stages (96KB), 128 threads = 4 warps in 2x2,
// warp tile 64x64 (halves LDSM traffic per MMA vs 32x64).
// Register-ring pipeline over the 4 k16 steps, bulk prefetch after step-0
// frag loads (R5 ordering). __launch_bounds__(128,2) -> 2 CTAs/SM.
// ============================================================================
static constexpr int BM = 128, BN = 128, BK = 64;
static constexpr int STAGES = 3;
static constexpr int A_STAGE = BM * BK * 2;   // 16384 B
static constexpr int B_STAGE = BN * BK * 2;   // 16384 B
static constexpr int GEMM_SMEM = STAGES * (A_STAGE + B_STAGE);  // 98304 B

__global__ void __launch_bounds__(128, 2) kron_gemm_kernel(
    float* __restrict__ out, const float* __restrict__ bias)
{
    extern __shared__ char smem[];
    const uint32_t smA = smem_to_u32(smem);
    const uint32_t smB = smA + STAGES * A_STAGE;

    const int tid  = threadIdx.x;
    const int wid  = tid >> 5;
    const int lane = tid & 31;
    const int wm   = wid & 1;   // 0..1 -> M (64 rows)
    const int wn   = wid >> 1;  // 0..1 -> N (64 cols)
    const int mBase = blockIdx.y * BM;
    const int nBase = blockIdx.x * BN;

    // cp.async: 128 rows x 8 chunks = 1024 chunks per operand; 8 per thread.
    const int c_row0 = tid >> 3;       // 0..15, strided by +16
    const int c_c    = tid & 7;

    const __half* Aptr = g_xh + ((size_t)mBase + c_row0) * KDIM + c_c * 8;
    const __half* Bptr = g_wt + ((size_t)nBase + c_row0) * KDIM + c_c * 8;
    const size_t rowStep = (size_t)16 * KDIM;

    uint32_t stOff[8];
    #pragma unroll
    for (int it = 0; it < 8; it++)
        stOff[it] = swz((uint32_t)(c_row0 + it * 16), (uint32_t)c_c);

    auto load_stage = [&](const __half* Ak, const __half* Bk, int slot) {
        uint32_t sA = smA + slot * A_STAGE;
        uint32_t sB = smB + slot * B_STAGE;
        #pragma unroll
        for (int it = 0; it < 8; it++)
            CP_ASYNC16(sA + stOff[it], Ak + it * rowStep);
        #pragma unroll
        for (int it = 0; it < 8; it++)
            CP_ASYNC16(sB + stOff[it], Bk + it * rowStep);
        CP_COMMIT();
    };

    #pragma unroll
    for (int s = 0; s < STAGES - 1; s++)
        load_stage(Aptr + s * BK, Bptr + s * BK, s);

    float acc[4][8][4] = {};   // 128 regs

    const int lm_row = lane & 15;
    const int lm_hi  = lane >> 4;

    uint32_t baseA[4], baseB[4];
    #pragma unroll
    for (int mi = 0; mi < 4; mi++)
        baseA[mi] = swz((uint32_t)(wm * 64 + mi * 16 + lm_row), 0) ^ ((uint32_t)lm_hi << 4);
    #pragma unroll
    for (int ni = 0; ni < 4; ni++)
        baseB[ni] = swz((uint32_t)(wn * 64 + ni * 16 + lm_row), 0) ^ ((uint32_t)lm_hi << 4);

    uint32_t afrag[2][4][4];   // [ring][mi][reg]
    uint32_t bfrag[2][4][4];   // [ring][ni][reg]

    auto load_frags = [&](uint32_t sA, uint32_t sB, int s, int buf) {
        const uint32_t cx = (uint32_t)(2 * s) << 4;
        #pragma unroll
        for (int mi = 0; mi < 4; mi++) ldmx4(afrag[buf][mi], sA + (baseA[mi] ^ cx));
        #pragma unroll
        for (int ni = 0; ni < 4; ni++) ldmx4(bfrag[buf][ni], sB + (baseB[ni] ^ cx));
    };

    auto do_mmas = [&](int buf) {
        #pragma unroll
        for (int mi = 0; mi < 4; mi++) {
            #pragma unroll
            for (int nj = 0; nj < 8; nj++) {
                const uint32_t* bg = bfrag[buf][nj >> 1];
                uint32_t b0 = (nj & 1) ? bg[1] : bg[0];
                uint32_t b1 = (nj & 1) ? bg[3] : bg[2];
                mma16816(acc[mi][nj], afrag[buf][mi], b0, b1);
            }
        }
    };

    const int KITERS = KDIM / BK;     // 64
    int slot = 0, nslot = STAGES - 1;
    #pragma unroll 1
    for (int kb = 0; kb < KITERS; kb++) {
        CP_WAIT(1);
        __syncthreads();

        const uint32_t sA = smA + slot * A_STAGE;
        const uint32_t sB = smB + slot * B_STAGE;

        load_frags(sA, sB, 0, 0);

        // Bulk prefetch of stage kb+2 (issued after the barrier -> slot free).
        const int kn = kb + STAGES - 1;
        if (kn < KITERS)
            load_stage(Aptr + kn * BK, Bptr + kn * BK, nslot);

        #pragma unroll
        for (int s = 0; s < 4; s++) {
            if (s < 3) load_frags(sA, sB, s + 1, (s + 1) & 1);
            do_mmas(s & 1);
        }

        slot = (slot == STAGES - 1) ? 0 : slot + 1;
        nslot = (nslot == STAGES - 1) ? 0 : nslot + 1;
    }

    // Epilogue
    const int gr = lane >> 2;
    const int gc = (lane & 3) * 2;
    float bv[8][2];
    #pragma unroll
    for (int nj = 0; nj < 8; nj++) {
        const int n0 = nBase + wn * 64 + nj * 8 + gc;
        bv[nj][0] = __ldg(&bias[n0]);
        bv[nj][1] = __ldg(&bias[n0 + 1]);
    }
    #pragma unroll
    for (int mi = 0; mi < 4; mi++) {
        const int m0 = mBase + wm * 64 + mi * 16 + gr;
        float* r0p = out + (size_t)m0 * NDIM;
        float* r1p = out + (size_t)(m0 + 8) * NDIM;
        #pragma unroll
        for (int nj = 0; nj < 8; nj++) {
            const int n0 = nBase + wn * 64 + nj * 8 + gc;
            float2 v0 = make_float2(acc[mi][nj][0] + bv[nj][0],
                                    acc[mi][nj][1] + bv[nj][1]);
            float2 v1 = make_float2(acc[mi][nj][2] + bv[nj][0],
                                    acc[mi][nj][3] + bv[nj][1]);
            *reinterpret_cast<float2*>(r0p + n0) = v0;
            *reinterpret_cast<float2*>(r1p + n0) = v1;
        }
    }
}

// ============================================================================
// kernel_launch
// ============================================================================
extern "C" void kernel_launch(void* const* d_in, const int* in_sizes, int n_in,
                              void* d_out, int out_size)
{
    const float* x    = (const float*)d_in[0];
    const float* a    = (const float*)d_in[1];
    const float* b    = (const float*)d_in[2];
    const float* bias = (const float*)d_in[3];
    float* out = (float*)d_out;

    static bool attr_set = false;
    if (!attr_set) {
        cudaFuncSetAttribute(kron_gemm_kernel,
                             cudaFuncAttributeMaxDynamicSharedMemorySize,
                             GEMM_SMEM);
        attr_set = true;
    }

    // 0. Transpose a, b into coalesced-read layouts
    transpose_ab_kernel<<<128, 256>>>(a, b);

    // 1. Materialize W^T in fp16 (register-blocked)
    build_wt_kernel<<<NDIM, 256>>>();

    // 2. Convert x to fp16
    convert_x_kernel<<<2048, 256>>>(x);

    // 3. Pipelined mma.sync fp16 GEMM with fused bias epilogue
    dim3 grid(NDIM / BN, NTOK / BM);   // (32, 64)
    kron_gemm_kernel<<<grid, 128, GEMM_SMEM>>>(out, bias);
}